// round 16
// baseline (speedup 1.0000x reference)
#include <cuda_runtime.h>
#include <cuda_bf16.h>
#include <math.h>

#define BTOT 32768
#define K 64
#define D 64
#define NF 2240            // padded feature count (140 k-steps of 16)
#define NQG 560            // feature quad-groups
#define NKS 140
#define NBLK_MAIN 256      // 128 samples per CTA, 256 threads (8 warps x 16 rows)

typedef unsigned long long ull;

// ---------------- device scratch (no allocs) ----------------
__device__ ull      d_Wf[NKS * 8 * 32];   // B fragments: e=(ks*8+nt)*32+lane
__device__ float    d_V[K][D][D];         // VT rows: d_V[k][j][i] = Linv[i][j]
__device__ float    d_b[K][D];
__device__ float    d_g[K];
__device__ float    d_partial[NBLK_MAIN];
__device__ unsigned d_count = 0;

// ---------------- helpers ----------------
__device__ __forceinline__ ull fma2(ull a, ull b, ull c) {
    ull d; asm("fma.rn.f32x2 %0, %1, %2, %3;" : "=l"(d) : "l"(a), "l"(b), "l"(c)); return d;
}
__device__ __forceinline__ float hadd2(ull a) {
    float lo, hi; asm("mov.b64 {%0, %1}, %2;" : "=f"(lo), "=f"(hi) : "l"(a)); return lo + hi;
}
__device__ __forceinline__ ull pack2(float lo, float hi) {
    ull d; asm("mov.b64 %0, {%1, %2};" : "=l"(d) : "f"(lo), "f"(hi)); return d;
}
__device__ __forceinline__ void lds2(ull& a, ull& b, unsigned addr) {
    asm("ld.shared.v2.b64 {%0, %1}, [%2];" : "=l"(a), "=l"(b) : "r"(addr));
}
// packs: lower 16 bits <- lo, upper <- hi
__device__ __forceinline__ unsigned cvt_bf16x2(float lo, float hi) {
    unsigned r;
    asm("cvt.rn.satfinite.bf16x2.f32 %0, %1, %2;" : "=r"(r) : "f"(hi), "f"(lo));
    return r;
}
__device__ __forceinline__ void mma_bf16(float& c0, float& c1, float& c2, float& c3,
                                         unsigned a0, unsigned a1, unsigned a2, unsigned a3,
                                         unsigned b0, unsigned b1) {
    asm volatile("mma.sync.aligned.m16n8k16.row.col.f32.bf16.bf16.f32 "
                 "{%0,%1,%2,%3}, {%4,%5,%6,%7}, {%8,%9}, {%0,%1,%2,%3};"
                 : "+f"(c0), "+f"(c1), "+f"(c2), "+f"(c3)
                 : "r"(a0), "r"(a1), "r"(a2), "r"(a3), "r"(b0), "r"(b1));
}

// ---------------------------------------------------------------------------
// Quad-group table (closed form). qg -> code (i<<8)|j0: the 4 features are
// x_i * x_{j0+e}, e=0..3.
//   qg < 16:  (64, 4*qg)  linear features (x[64]=1)
//   qg >= 16: tri rows; row i has floor(i/4)+1 quads; j>i are pads (W=0).
// Prefix quads before row i=4m+r: 2m(m+1) + r(m+1).
// ---------------------------------------------------------------------------
__device__ __forceinline__ int quad_code(int g) {
    if (g < 16) return (64 << 8) | (4 * g);
    int G = g - 16;
    int m = (int)((sqrtf(8.0f * (float)G + 4.0f) - 2.0f) * 0.25f);
    if (m < 0) m = 0;
    if (m > 15) m = 15;
    while (m < 15 && 2 * (m + 1) * (m + 2) <= G) ++m;
    while (m > 0 && 2 * m * (m + 1) > G) --m;
    int rem = G - 2 * m * (m + 1);
    int r = rem / (m + 1);
    int j0 = 4 * (rem - r * (m + 1));
    int i = 4 * m + r;
    return (i << 8) | j0;
}

// ---------------------------------------------------------------------------
// prep1: one 128-thread block per component k.
//   L -> Linv (forward substitution, unroll-4 pipelined), store VT to gmem.
//   b = V^T (V mu) via two matvecs; g via warp-shuffle reductions.
// ---------------------------------------------------------------------------
__global__ __launch_bounds__(128) void prep1_kernel(const float* __restrict__ scale_raw,
                                                    const float* __restrict__ means_raw,
                                                    const float* __restrict__ weights_raw) {
    const int k = blockIdx.x;
    const int tid = threadIdx.x;

    __shared__ float Ls[D][D];
    __shared__ float VT[D][68];    // VT[j][i] = Linv[i][j]
    __shared__ float rdiag[D], ms[D], pdiag[D], w1s[D], wsh[D];
    __shared__ float wstage[K];

    const float sc2 = 1.0f / 512.0f;
    const float sc1 = 1.0f / 64.0f;

    for (int idx = tid; idx < D * D; idx += 128) {
        int i = idx >> 6, jj = idx & 63;
        float p = scale_raw[(size_t)k * D * D + idx] * sc2;
        float v;
        if (jj < i) v = p;
        else if (jj == i) { float e = expf(p); v = e; pdiag[i] = p; rdiag[i] = 1.0f / e; }
        else v = 0.0f;
        Ls[i][jj] = v;
    }
    if (tid < D) ms[tid] = means_raw[k * D + tid] * sc1;
    if (tid < K) wstage[tid] = weights_raw[tid] * 0.125f;
    __syncthreads();

    // forward substitution: thread j (<64) computes column j into VT[j][*]
    if (tid < D) {
        const int j = tid;
        float prev = 0.0f;
        #pragma unroll 1
        for (int i = 0; i < D; ++i) {
            const float* Lrow = &Ls[i][0];
            const int e = i - 1;
            const int mend = (e > 0) ? (e & ~3) : 0;
            float a0 = 0.f, a1 = 0.f, a2 = 0.f, a3 = 0.f;
            #pragma unroll 4
            for (int m = 0; m < mend; m += 4) {
                float4 vm = *(const float4*)&VT[j][m];
                a0 = fmaf(Lrow[m + 0], vm.x, a0);
                a1 = fmaf(Lrow[m + 1], vm.y, a1);
                a2 = fmaf(Lrow[m + 2], vm.z, a2);
                a3 = fmaf(Lrow[m + 3], vm.w, a3);
            }
            for (int m = mend; m < e; ++m) a0 = fmaf(Lrow[m], VT[j][m], a0);
            float s = (a0 + a1) + (a2 + a3);
            if (i > 0) s = fmaf(Lrow[e], prev, s);
            float de = (j == i) ? 1.0f : 0.0f;
            float vi = (de - s) * rdiag[i];
            VT[j][i] = vi;
            prev = vi;
        }
    }
    __syncthreads();

    // store VT to gmem (coalesced float4)
    {
        float4* dst = (float4*)&d_V[k][0][0];
        for (int idx = tid; idx < D * D / 4; idx += 128) {
            int row = idx >> 4, c4 = idx & 15;
            dst[idx] = *(const float4*)&VT[row][c4 * 4];
        }
    }

    // w1 = V mu: w1_i = sum_j VT[j][i] * mu_j  (strided reads, 4 accumulators)
    if (tid < D) {
        const int i = tid;
        float a0 = 0.f, a1 = 0.f, a2 = 0.f, a3 = 0.f;
        #pragma unroll 4
        for (int j = 0; j < D; j += 4) {
            a0 = fmaf(VT[j + 0][i], ms[j + 0], a0);
            a1 = fmaf(VT[j + 1][i], ms[j + 1], a1);
            a2 = fmaf(VT[j + 2][i], ms[j + 2], a2);
            a3 = fmaf(VT[j + 3][i], ms[j + 3], a3);
        }
        w1s[i] = (a0 + a1) + (a2 + a3);
    }
    __syncthreads();

    // b_j = sum_i VT[j][i] * w1_i  (contiguous row)
    if (tid < D) {
        const int j = tid;
        float a0 = 0.f, a1 = 0.f, a2 = 0.f, a3 = 0.f;
        #pragma unroll 4
        for (int i = 0; i < D; i += 4) {
            float4 vm = *(const float4*)&VT[j][i];
            float4 wm = *(const float4*)&w1s[i];
            a0 = fmaf(vm.x, wm.x, a0);
            a1 = fmaf(vm.y, wm.y, a1);
            a2 = fmaf(vm.z, wm.z, a2);
            a3 = fmaf(vm.w, wm.w, a3);
        }
        float bj = (a0 + a1) + (a2 + a3);
        d_b[k][j] = bj;
        wsh[j] = ms[j] * bj;
    }
    __syncthreads();

    // tail reductions in warp 0 (shfl)
    if (tid < 32) {
        float h2 = pdiag[tid] + pdiag[tid + 32];
        float c2 = wsh[tid] + wsh[tid + 32];
        float w1 = wstage[tid], w2 = wstage[tid + 32];
        float wm = fmaxf(w1, w2);
        #pragma unroll
        for (int o = 16; o > 0; o >>= 1) wm = fmaxf(wm, __shfl_xor_sync(0xFFFFFFFFu, wm, o));
        float es = __expf(w1 - wm) + __expf(w2 - wm);
        #pragma unroll
        for (int o = 16; o > 0; o >>= 1) {
            es += __shfl_xor_sync(0xFFFFFFFFu, es, o);
            h2 += __shfl_xor_sync(0xFFFFFFFFu, h2, o);
            c2 += __shfl_xor_sync(0xFFFFFFFFu, c2, o);
        }
        if (tid == 0) {
            float logwk = wstage[k] - (wm + logf(es));
            const float HALF_D_LOG2PI = 0.5f * 64.0f * 1.8378770664093453f;
            d_g[k] = logwk - h2 - HALF_D_LOG2PI - 0.5f * c2;
        }
    }
}

// ---------------------------------------------------------------------------
// prep2: one 256-thread block per component k. Each thread computes ~9 W
// entries directly: A[i][j] = dot(VT row i, VT row j) (A never materialized),
// scatters bf16 into d_Wf fragment layout.
// ---------------------------------------------------------------------------
__global__ __launch_bounds__(256) void prep2_kernel() {
    const int kc = blockIdx.x;
    const int tid = threadIdx.x;

    __shared__ float VTs[D][68];
    __shared__ float bsh[D];

    {
        const float4* src = (const float4*)&d_V[kc][0][0];
        for (int idx = tid; idx < D * D / 4; idx += 256) {
            int row = idx >> 4, c4 = idx & 15;
            *(float4*)&VTs[row][c4 * 4] = src[idx];
        }
        if (tid < D) bsh[tid] = d_b[kc][tid];
    }
    __syncthreads();

    const unsigned vtb = (unsigned)__cvta_generic_to_shared(&VTs[0][0]);

    for (int f = tid; f < NF; f += 256) {
        const int g = f >> 2, e = f & 3;
        const int code = quad_code(g);
        const int i = code >> 8, j = (code & 255) + e;
        float w;
        if (i == 64) {
            w = bsh[j];                       // linear: b_j
        } else if (j > i) {
            w = 0.0f;                          // pad
        } else {
            // dot(VT row i, VT row j) via f32x2
            const unsigned ra = vtb + (unsigned)i * 272u;
            const unsigned rb = vtb + (unsigned)j * 272u;
            ull acc = 0ULL;
            #pragma unroll
            for (int c = 0; c < 16; ++c) {
                ull p0, p1, q0, q1;
                lds2(p0, p1, ra + 16u * c);
                lds2(q0, q1, rb + 16u * c);
                acc = fma2(p0, q0, acc);
                acc = fma2(p1, q1, acc);
            }
            float a = hadd2(acc);
            w = (j == i) ? -0.5f * (a - 1.0f) : -a;
        }
        // fragment scatter: within = e<2 ? 2q+e : 8+2q+(e-2), q = g&3
        const int ks = f >> 4;
        const int q = g & 3;
        const int wi = (e < 2) ? (2 * q + e) : (8 + 2 * q + (e - 2));
        const int hh = wi >> 3, bb = wi & 1, qq = (wi & 7) >> 1;
        const int lane = ((kc & 7) << 2) | qq;
        const int ent = (ks * 8 + (kc >> 3)) * 32 + lane;
        ((__nv_bfloat16*)d_Wf)[ent * 4 + hh * 2 + bb] = __float2bfloat16(w);
    }
}

// ---------------------------------------------------------------------------
// main: 256 CTAs x 256 threads (8 warps x 16 rows). Quad-group features:
// per k-step per lane: 1 table read + 2 scalar LDS + 2 LDS.128.
// ---------------------------------------------------------------------------
#define DO_STEP(KS, BARR)                                                     \
    do {                                                                      \
        const int t0 = sgrp[(KS) * 4 + q];                                    \
        const int iA = t0 >> 8, jA = t0 & 255;                                \
        float  s0 = rp0[iA]; float4 v0 = *(const float4*)(rp0 + jA);          \
        float  s1 = rp1[iA]; float4 v1 = *(const float4*)(rp1 + jA);          \
        const unsigned a0 = cvt_bf16x2(s0 * v0.x, s0 * v0.y);                 \
        const unsigned a1 = cvt_bf16x2(s1 * v1.x, s1 * v1.y);                 \
        const unsigned a2 = cvt_bf16x2(s0 * v0.z, s0 * v0.w);                 \
        const unsigned a3 = cvt_bf16x2(s1 * v1.z, s1 * v1.w);                 \
        _Pragma("unroll")                                                     \
        for (int nt = 0; nt < 8; ++nt) {                                      \
            const unsigned b0 = (unsigned)(BARR[nt] & 0xFFFFFFFFu);           \
            const unsigned b1 = (unsigned)(BARR[nt] >> 32);                   \
            mma_bf16(acc[nt][0], acc[nt][1], acc[nt][2], acc[nt][3],          \
                     a0, a1, a2, a3, b0, b1);                                 \
        }                                                                     \
    } while (0)

__global__ __launch_bounds__(256, 2) void gmm_main(const float* __restrict__ x,
                                                   float* __restrict__ out) {
    __shared__ float xs[128][68];      // row: 64 x values, [64]=1
    __shared__ float xxs[128];
    __shared__ float gs[K];
    __shared__ int   sgrp[NQG];
    __shared__ float red[256];
    __shared__ unsigned sflag;

    const int tid = threadIdx.x;
    const int wid = tid >> 5, lane = tid & 31;
    const int q = lane & 3, ro = lane >> 2;

    for (int g = tid; g < NQG; g += 256) sgrp[g] = quad_code(g);

    if (tid < 128) {
        const float4* xg = (const float4*)(x + ((size_t)blockIdx.x * 128 + tid) * D);
        float xx = 0.0f;
        float4* xrow = (float4*)&xs[tid][0];
        #pragma unroll
        for (int i = 0; i < 16; ++i) {
            float4 v = xg[i];
            xrow[i] = v;
            xx = fmaf(v.x, v.x, xx); xx = fmaf(v.y, v.y, xx);
            xx = fmaf(v.z, v.z, xx); xx = fmaf(v.w, v.w, xx);
        }
        xs[tid][64] = 1.0f; xs[tid][65] = 0.0f;
        xs[tid][66] = 0.0f; xs[tid][67] = 0.0f;
        xxs[tid] = xx;
    }
    if (tid < K) gs[tid] = d_g[tid];
    __syncthreads();

    const int wbase = wid * 16;
    const float* rp0 = &xs[wbase + ro][0];
    const float* rp1 = &xs[wbase + ro + 8][0];

    float acc[8][4];
    #pragma unroll
    for (int nt = 0; nt < 8; ++nt)
        #pragma unroll
        for (int c = 0; c < 4; ++c) acc[nt][c] = 0.0f;

    const ull* wf = d_Wf + lane;

    ull bA[8], bB[8];
    #pragma unroll
    for (int nt = 0; nt < 8; ++nt) bA[nt] = wf[nt * 32];

    #pragma unroll 1
    for (int ks = 0; ks < NKS; ks += 2) {
        #pragma unroll
        for (int nt = 0; nt < 8; ++nt) bB[nt] = wf[(ks + 1) * 256 + nt * 32];
        DO_STEP(ks, bA);
        const int k2 = (ks + 2 < NKS) ? ks + 2 : NKS - 1;
        #pragma unroll
        for (int nt = 0; nt < 8; ++nt) bA[nt] = wf[k2 * 256 + nt * 32];
        DO_STEP(ks + 1, bB);
    }

    // epilogue: per thread 2 rows x 16 comps; quad-shuffle LSE per row
    float lpsum = 0.0f;
    #pragma unroll
    for (int hf = 0; hf < 2; ++hf) {
        const int row = wbase + ro + 8 * hf;
        const float cxx = -0.5f * xxs[row];
        float v[16];
        float m = -1e30f;
        #pragma unroll
        for (int nt = 0; nt < 8; ++nt) {
            #pragma unroll
            for (int cc = 0; cc < 2; ++cc) {
                float val = acc[nt][hf * 2 + cc] + gs[nt * 8 + q * 2 + cc] + cxx;
                v[nt * 2 + cc] = val;
                m = fmaxf(m, val);
            }
        }
        m = fmaxf(m, __shfl_xor_sync(0xFFFFFFFFu, m, 1));
        m = fmaxf(m, __shfl_xor_sync(0xFFFFFFFFu, m, 2));
        float s = 0.0f;
        #pragma unroll
        for (int u = 0; u < 16; ++u) s += __expf(v[u] - m);
        s += __shfl_xor_sync(0xFFFFFFFFu, s, 1);
        s += __shfl_xor_sync(0xFFFFFFFFu, s, 2);
        lpsum += m + logf(s);
    }
    red[tid] = (q == 0) ? lpsum : 0.0f;
    __syncthreads();
    #pragma unroll
    for (int s = 128; s > 0; s >>= 1) {
        if (tid < s) red[tid] += red[tid + s];
        __syncthreads();
    }
    if (tid == 0) {
        d_partial[blockIdx.x] = red[0];
        __threadfence();
        unsigned ticket = atomicAdd(&d_count, 1u);
        sflag = (ticket == (unsigned)(NBLK_MAIN - 1)) ? 1u : 0u;
    }
    __syncthreads();

    if (sflag) {
        __threadfence();
        red[tid] = d_partial[tid];
        __syncthreads();
        #pragma unroll
        for (int s = 128; s > 0; s >>= 1) {
            if (tid < s) red[tid] += red[tid + s];
            __syncthreads();
        }
        if (tid == 0) {
            out[0] = -red[0] / (float)BTOT;
            d_count = 0;                      // reset for next graph replay
        }
    }
}

extern "C" void kernel_launch(void* const* d_in, const int* in_sizes, int n_in,
                              void* d_out, int out_size) {
    const float* x      = (const float*)d_in[0];
    const float* means  = (const float*)d_in[1];
    const float* scale  = (const float*)d_in[2];
    const float* wraw   = (const float*)d_in[3];

    prep1_kernel<<<K, 128>>>(scale, means, wraw);
    prep2_kernel<<<K, 256>>>();
    gmm_main<<<NBLK_MAIN, 256>>>(x, (float*)d_out);
}